// round 2
// baseline (speedup 1.0000x reference)
#include <cuda_runtime.h>
#include <math.h>

// Problem constants (fixed by setup_inputs)
#define SEQ   4096
#define HID   2048
#define NHQ   32
#define NHKV  4
#define DH    128
#define DQTOT (NHQ*DH)    // 4096
#define DKVTOT (NHKV*DH)  // 512

// ---------------------------------------------------------------------------
// Scratch (device globals; no cudaMalloc allowed)
// ---------------------------------------------------------------------------
__device__ float g_Q[SEQ * DQTOT];   // 64 MB
__device__ float g_K[SEQ * DKVTOT];  // 8 MB
__device__ float g_V[SEQ * DKVTOT];  // 8 MB
__device__ float g_O[SEQ * DQTOT];   // 64 MB

// ---------------------------------------------------------------------------
// Tiled fp32 GEMM: C[M,N] = A[M,K] @ B[K,N], all row-major.
// 128x128 tile, BK=16, 256 threads, 8x8 micro-tile per thread.
// ---------------------------------------------------------------------------
__global__ __launch_bounds__(256) void sgemm128(
    const float* __restrict__ A, const float* __restrict__ B,
    float* __restrict__ C, int M, int N, int K)
{
    __shared__ float As[16][132];  // transposed A tile (padded)
    __shared__ float Bs[16][128];

    const int tid = threadIdx.x;
    const int tx = tid & 15;
    const int ty = tid >> 4;
    const int m0 = blockIdx.y * 128;
    const int n0 = blockIdx.x * 128;

    float acc[8][8];
#pragma unroll
    for (int i = 0; i < 8; i++)
#pragma unroll
        for (int j = 0; j < 8; j++) acc[i][j] = 0.f;

    for (int k0 = 0; k0 < K; k0 += 16) {
#pragma unroll
        for (int l = 0; l < 2; l++) {
            int t = tid + l * 256;
            // A tile: 128 rows x 16 cols -> transposed into As
            int ra = t >> 2;
            int ca = (t & 3) << 2;
            float4 av = *(const float4*)&A[(size_t)(m0 + ra) * K + k0 + ca];
            As[ca + 0][ra] = av.x;
            As[ca + 1][ra] = av.y;
            As[ca + 2][ra] = av.z;
            As[ca + 3][ra] = av.w;
            // B tile: 16 rows x 128 cols
            int rb = t >> 5;
            int cb = (t & 31) << 2;
            *(float4*)&Bs[rb][cb] = *(const float4*)&B[(size_t)(k0 + rb) * N + n0 + cb];
        }
        __syncthreads();

#pragma unroll
        for (int kk = 0; kk < 16; kk++) {
            float a[8], b[8];
            *(float4*)&a[0] = *(float4*)&As[kk][ty * 4];
            *(float4*)&a[4] = *(float4*)&As[kk][64 + ty * 4];
            *(float4*)&b[0] = *(float4*)&Bs[kk][tx * 4];
            *(float4*)&b[4] = *(float4*)&Bs[kk][64 + tx * 4];
#pragma unroll
            for (int i = 0; i < 8; i++)
#pragma unroll
                for (int j = 0; j < 8; j++)
                    acc[i][j] += a[i] * b[j];
        }
        __syncthreads();
    }

#pragma unroll
    for (int i = 0; i < 8; i++) {
        int row = m0 + ((i < 4) ? (ty * 4 + i) : (64 + ty * 4 + (i - 4)));
        float4 c0 = make_float4(acc[i][0], acc[i][1], acc[i][2], acc[i][3]);
        float4 c1 = make_float4(acc[i][4], acc[i][5], acc[i][6], acc[i][7]);
        *(float4*)&C[(size_t)row * N + n0 + tx * 4] = c0;
        *(float4*)&C[(size_t)row * N + n0 + 64 + tx * 4] = c1;
    }
}

// ---------------------------------------------------------------------------
// RoPE (rotate-half, max_wavelength 10000), applied in place.
// grid: (SEQ, nheads), 64 threads; thread d handles the (d, d+64) pair.
// ---------------------------------------------------------------------------
__global__ void rope_kernel(float* __restrict__ X, const int* __restrict__ pos, int stride)
{
    const int s = blockIdx.x;
    const int h = blockIdx.y;
    const int d = threadIdx.x;  // 0..63

    float p = (float)pos[s];
    float inv = powf(10000.0f, -(float)d / 64.0f);
    float sn, cs;
    sincosf(p * inv, &sn, &cs);

    float* base = X + (size_t)s * stride + h * DH;
    float x1 = base[d];
    float x2 = base[d + 64];
    base[d]      = x1 * cs - x2 * sn;
    base[d + 64] = x2 * cs + x1 * sn;
}

// ---------------------------------------------------------------------------
// Causal flash attention, fp32, GQA (8 q-heads per kv-head).
// grid: (SEQ/64, NHQ); 256 threads; 64 q-rows per CTA, 64-wide KV tiles.
// Q/K/V tiles live in XOR-swizzled smem (pitch 128 floats, no padding).
// ---------------------------------------------------------------------------
#define FLASH_SMEM_FLOATS (3 * 64 * 128 + 64 * 65)
#define FLASH_SMEM_BYTES  (FLASH_SMEM_FLOATS * 4)

__device__ __forceinline__ int swz(int row, int c4) {
    // c4 is a multiple of 4 (float4-granular). XOR-swizzle on float4 slot.
    return row * 128 + ((((c4 >> 2) ^ ((row >> 2) & 7)) << 2) | (c4 & 3));
}

__device__ __forceinline__ void load_tile64x128(
    float* __restrict__ dst, const float* __restrict__ src,
    int row0, int stride, int tid)
{
#pragma unroll
    for (int l = 0; l < 8; l++) {
        int t = tid + l * 256;
        int r = t >> 5;
        int c4 = (t & 31) << 2;
        int sw = r * 128 + ((((c4 >> 2) ^ ((r >> 2) & 7)) << 2));
        *(float4*)&dst[sw] = *(const float4*)&src[(size_t)(row0 + r) * stride + c4];
    }
}

__global__ __launch_bounds__(256) void flash_kernel(
    const float* __restrict__ Q, const float* __restrict__ K,
    const float* __restrict__ V, float* __restrict__ O)
{
    extern __shared__ float sm[];
    float* qs = sm;                 // [64][128] swizzled
    float* ks = qs + 64 * 128;      // [64][128] swizzled
    float* vs = ks + 64 * 128;      // [64][128] swizzled
    float* ps = vs + 64 * 128;      // [64][65]

    const int qb = (gridDim.x - 1) - blockIdx.x;  // heavy blocks first
    const int h  = blockIdx.y;
    const int hk = h >> 3;
    const int tid = threadIdx.x;
    const int tx = tid & 15;
    const int ty = tid >> 4;
    const int qrow0 = ty * 4;

    const float* Qh = Q + (size_t)h * DH;
    const float* Kh = K + (size_t)hk * DH;
    const float* Vh = V + (size_t)hk * DH;

    load_tile64x128(qs, Qh, qb * 64, DQTOT, tid);

    float m[4], lsum[4], o[4][8];
#pragma unroll
    for (int i = 0; i < 4; i++) {
        m[i] = -1e30f;
        lsum[i] = 0.f;
#pragma unroll
        for (int j = 0; j < 8; j++) o[i][j] = 0.f;
    }

    const float scale = 0.08838834764831845f;  // 1/sqrt(128)

    for (int kb = 0; kb <= qb; kb++) {
        __syncthreads();  // prior PV done; safe to overwrite ks/vs
        load_tile64x128(ks, Kh, kb * 64, DKVTOT, tid);
        load_tile64x128(vs, Vh, kb * 64, DKVTOT, tid);
        __syncthreads();

        // S = Q @ K^T for this 64x64 tile; thread owns 4x4
        float sacc[4][4];
#pragma unroll
        for (int i = 0; i < 4; i++)
#pragma unroll
            for (int j = 0; j < 4; j++) sacc[i][j] = 0.f;

#pragma unroll 4
        for (int d4 = 0; d4 < 128; d4 += 4) {
            int qsw = (((d4 >> 2) ^ (ty & 7)) << 2);
            int ksw = (((d4 >> 2) ^ (tx & 7)) << 2);
            float4 qv[4], kv[4];
#pragma unroll
            for (int i = 0; i < 4; i++)
                qv[i] = *(float4*)&qs[(qrow0 + i) * 128 + qsw];
#pragma unroll
            for (int j = 0; j < 4; j++)
                kv[j] = *(float4*)&ks[(tx * 4 + j) * 128 + ksw];
#pragma unroll
            for (int i = 0; i < 4; i++)
#pragma unroll
                for (int j = 0; j < 4; j++)
                    sacc[i][j] += qv[i].x * kv[j].x + qv[i].y * kv[j].y
                                + qv[i].z * kv[j].z + qv[i].w * kv[j].w;
        }

        // online softmax
        const int grow = qb * 64 + qrow0;
        const int gcol = kb * 64 + tx * 4;
#pragma unroll
        for (int i = 0; i < 4; i++) {
            float mx = -1e30f;
#pragma unroll
            for (int j = 0; j < 4; j++) {
                float sv = sacc[i][j] * scale;
                if (gcol + j > grow + i) sv = -1e30f;
                sacc[i][j] = sv;
                mx = fmaxf(mx, sv);
            }
#pragma unroll
            for (int off = 8; off; off >>= 1)
                mx = fmaxf(mx, __shfl_xor_sync(0xffffffffu, mx, off));
            float mnew = fmaxf(m[i], mx);
            float f = __expf(m[i] - mnew);
            m[i] = mnew;
            float rs = 0.f;
#pragma unroll
            for (int j = 0; j < 4; j++) {
                float p = __expf(sacc[i][j] - mnew);
                ps[(qrow0 + i) * 65 + tx * 4 + j] = p;
                rs += p;
            }
#pragma unroll
            for (int off = 8; off; off >>= 1)
                rs += __shfl_xor_sync(0xffffffffu, rs, off);
            lsum[i] = lsum[i] * f + rs;
#pragma unroll
            for (int jj = 0; jj < 8; jj++) o[i][jj] *= f;
        }
        __syncthreads();  // ps visible to everyone

        // O += P @ V  (thread owns rows qrow0..+3, cols tx*8..+7)
#pragma unroll 2
        for (int kk = 0; kk < 64; kk++) {
            float pr[4];
#pragma unroll
            for (int i = 0; i < 4; i++) pr[i] = ps[(qrow0 + i) * 65 + kk];
            int x = (kk >> 2) & 7;
            float4 v0 = *(float4*)&vs[kk * 128 + ((((tx * 2)     ^ x)) << 2)];
            float4 v1 = *(float4*)&vs[kk * 128 + ((((tx * 2 + 1) ^ x)) << 2)];
#pragma unroll
            for (int i = 0; i < 4; i++) {
                o[i][0] += pr[i] * v0.x;  o[i][1] += pr[i] * v0.y;
                o[i][2] += pr[i] * v0.z;  o[i][3] += pr[i] * v0.w;
                o[i][4] += pr[i] * v1.x;  o[i][5] += pr[i] * v1.y;
                o[i][6] += pr[i] * v1.z;  o[i][7] += pr[i] * v1.w;
            }
        }
    }

    // epilogue: normalize and store to g_O[s, h*128 + d]
#pragma unroll
    for (int i = 0; i < 4; i++) {
        float inv = 1.0f / lsum[i];
        size_t row = (size_t)(qb * 64 + qrow0 + i);
        float4 r0 = make_float4(o[i][0] * inv, o[i][1] * inv, o[i][2] * inv, o[i][3] * inv);
        float4 r1 = make_float4(o[i][4] * inv, o[i][5] * inv, o[i][6] * inv, o[i][7] * inv);
        *(float4*)&O[row * DQTOT + h * DH + tx * 8]     = r0;
        *(float4*)&O[row * DQTOT + h * DH + tx * 8 + 4] = r1;
    }
}

// ---------------------------------------------------------------------------
// Launch
// ---------------------------------------------------------------------------
extern "C" void kernel_launch(void* const* d_in, const int* in_sizes, int n_in,
                              void* d_out, int out_size)
{
    const float* X  = (const float*)d_in[0];
    const float* Wq = (const float*)d_in[1];
    const float* Wk = (const float*)d_in[2];
    const float* Wv = (const float*)d_in[3];
    const float* Wo = (const float*)d_in[4];
    const int*  pos = (const int*)d_in[5];
    float* out = (float*)d_out;

    float *Qp, *Kp, *Vp, *Op;
    cudaGetSymbolAddress((void**)&Qp, g_Q);
    cudaGetSymbolAddress((void**)&Kp, g_K);
    cudaGetSymbolAddress((void**)&Vp, g_V);
    cudaGetSymbolAddress((void**)&Op, g_O);

    cudaFuncSetAttribute(flash_kernel,
                         cudaFuncAttributeMaxDynamicSharedMemorySize,
                         FLASH_SMEM_BYTES);

    // QKV projections
    sgemm128<<<dim3(DQTOT / 128, SEQ / 128), 256>>>(X, Wq, Qp, SEQ, DQTOT, HID);
    sgemm128<<<dim3(DKVTOT / 128, SEQ / 128), 256>>>(X, Wk, Kp, SEQ, DKVTOT, HID);
    sgemm128<<<dim3(DKVTOT / 128, SEQ / 128), 256>>>(X, Wv, Vp, SEQ, DKVTOT, HID);

    // RoPE on Q and K
    rope_kernel<<<dim3(SEQ, NHQ), 64>>>(Qp, pos, DQTOT);
    rope_kernel<<<dim3(SEQ, NHKV), 64>>>(Kp, pos, DKVTOT);

    // causal flash attention
    flash_kernel<<<dim3(SEQ / 64, NHQ), 256, FLASH_SMEM_BYTES>>>(Qp, Kp, Vp, Op);

    // output projection
    sgemm128<<<dim3(HID / 128, SEQ / 128), 256>>>(Op, Wo, out, SEQ, HID, DQTOT);
}

// round 3
// speedup vs baseline: 1.7725x; 1.7725x over previous
#include <cuda_runtime.h>
#include <math.h>
#include <stdint.h>

// Problem constants (fixed by setup_inputs)
#define SEQ   4096
#define HID   2048
#define NHQ   32
#define NHKV  4
#define DH    128
#define DQTOT (NHQ*DH)    // 4096
#define DKVTOT (NHKV*DH)  // 512

// ---------------------------------------------------------------------------
// Scratch (device globals; no cudaMalloc allowed)
// ---------------------------------------------------------------------------
__device__ float g_Q[SEQ * DQTOT];   // 64 MB
__device__ float g_K[SEQ * DKVTOT];  // 8 MB
__device__ float g_V[SEQ * DKVTOT];  // 8 MB
__device__ float g_O[SEQ * DQTOT];   // 64 MB

// ---------------------------------------------------------------------------
// tf32 helpers
// ---------------------------------------------------------------------------
__device__ __forceinline__ uint32_t f2tf(float x) {
    uint32_t u;
    asm("cvt.rna.tf32.f32 %0, %1;" : "=r"(u) : "f"(x));
    return u;
}

__device__ __forceinline__ void splitf(float x, uint32_t& hi, uint32_t& lo) {
    hi = f2tf(x);
    lo = f2tf(x - __uint_as_float(hi));
}

__device__ __forceinline__ void mma8(float* c, const uint32_t* a, const uint32_t* b) {
    asm volatile(
        "mma.sync.aligned.m16n8k8.row.col.f32.tf32.tf32.f32 "
        "{%0,%1,%2,%3}, {%4,%5,%6,%7}, {%8,%9}, {%0,%1,%2,%3};\n"
        : "+f"(c[0]), "+f"(c[1]), "+f"(c[2]), "+f"(c[3])
        : "r"(a[0]), "r"(a[1]), "r"(a[2]), "r"(a[3]), "r"(b[0]), "r"(b[1]));
}

__device__ __forceinline__ void cp16(uint32_t dst, const void* src) {
    asm volatile("cp.async.ca.shared.global [%0], [%1], 16;\n" :: "r"(dst), "l"(src));
}
__device__ __forceinline__ void cp_commit() { asm volatile("cp.async.commit_group;\n"); }
__device__ __forceinline__ void cp_wait0()  { asm volatile("cp.async.wait_group 0;\n"); }

// ---------------------------------------------------------------------------
// tf32 tensor-core GEMM: C[M,N] = A[M,K] @ B[K,N], row-major.
// 128x128 tile, BK=16, 256 threads (8 warps as 2x4), warp tile 64x32.
// NPASS=3: error-compensated 3xTF32 (hi/lo split on both operands).
// ---------------------------------------------------------------------------
#define A_PITCH 20
#define B_PITCH 136

template<int NPASS>
__global__ __launch_bounds__(256) void tgemm(
    const float* __restrict__ A, const float* __restrict__ B,
    float* __restrict__ C, int M, int N, int K)
{
    __shared__ float As[2][128 * A_PITCH];
    __shared__ float Bs[2][16 * B_PITCH];

    const int tid  = threadIdx.x;
    const int lane = tid & 31;
    const int w    = tid >> 5;
    const int wm   = w >> 2;   // 0..1
    const int wn   = w & 3;    // 0..3
    const int m0   = blockIdx.y * 128;
    const int n0   = blockIdx.x * 128;
    const int gid  = lane >> 2;   // groupID (row within fragment)
    const int tig  = lane & 3;    // thread-in-group (col within fragment)

    float c[4][4][4];
#pragma unroll
    for (int mt = 0; mt < 4; mt++)
#pragma unroll
        for (int nt = 0; nt < 4; nt++)
#pragma unroll
            for (int q = 0; q < 4; q++) c[mt][nt][q] = 0.f;

    uint32_t asBase[2], bsBase[2];
#pragma unroll
    for (int b = 0; b < 2; b++) {
        asBase[b] = (uint32_t)__cvta_generic_to_shared(&As[b][0]);
        bsBase[b] = (uint32_t)__cvta_generic_to_shared(&Bs[b][0]);
    }

    auto loadTiles = [&](int k0, int buf) {
#pragma unroll
        for (int l = 0; l < 2; l++) {
            int i = tid + l * 256;
            int r = i >> 2, c4 = (i & 3) << 2;
            cp16(asBase[buf] + (r * A_PITCH + c4) * 4,
                 A + (size_t)(m0 + r) * K + k0 + c4);
        }
#pragma unroll
        for (int l = 0; l < 2; l++) {
            int i = tid + l * 256;
            int r = i >> 5, c4 = (i & 31) << 2;
            cp16(bsBase[buf] + (r * B_PITCH + c4) * 4,
                 B + (size_t)(k0 + r) * N + n0 + c4);
        }
    };

    const int NT = K / 16;
    loadTiles(0, 0);
    cp_commit();

    for (int t = 0; t < NT; t++) {
        cp_wait0();
        __syncthreads();
        if (t + 1 < NT) {
            loadTiles((t + 1) * 16, (t + 1) & 1);
            cp_commit();
        }
        const int buf = t & 1;
        const float* as = As[buf];
        const float* bs = Bs[buf];

#pragma unroll
        for (int kk = 0; kk < 2; kk++) {
            const int kb = kk * 8;
            uint32_t ahi[4][4], alo[4][4];
#pragma unroll
            for (int mt = 0; mt < 4; mt++) {
                int rm = wm * 64 + mt * 16 + gid;
                int kc = kb + tig;
                float x0 = as[rm * A_PITCH + kc];
                float x1 = as[(rm + 8) * A_PITCH + kc];
                float x2 = as[rm * A_PITCH + kc + 4];
                float x3 = as[(rm + 8) * A_PITCH + kc + 4];
                if (NPASS == 3) {
                    splitf(x0, ahi[mt][0], alo[mt][0]);
                    splitf(x1, ahi[mt][1], alo[mt][1]);
                    splitf(x2, ahi[mt][2], alo[mt][2]);
                    splitf(x3, ahi[mt][3], alo[mt][3]);
                } else {
                    ahi[mt][0] = f2tf(x0); ahi[mt][1] = f2tf(x1);
                    ahi[mt][2] = f2tf(x2); ahi[mt][3] = f2tf(x3);
                }
            }
            uint32_t bhi[4][2], blo[4][2];
#pragma unroll
            for (int nt = 0; nt < 4; nt++) {
                int nc = wn * 32 + nt * 8 + gid;
                float y0 = bs[(kb + tig) * B_PITCH + nc];
                float y1 = bs[(kb + tig + 4) * B_PITCH + nc];
                if (NPASS == 3) {
                    splitf(y0, bhi[nt][0], blo[nt][0]);
                    splitf(y1, bhi[nt][1], blo[nt][1]);
                } else {
                    bhi[nt][0] = f2tf(y0); bhi[nt][1] = f2tf(y1);
                }
            }
#pragma unroll
            for (int mt = 0; mt < 4; mt++)
#pragma unroll
                for (int nt = 0; nt < 4; nt++) {
                    mma8(c[mt][nt], ahi[mt], bhi[nt]);
                    if (NPASS == 3) {
                        mma8(c[mt][nt], ahi[mt], blo[nt]);
                        mma8(c[mt][nt], alo[mt], bhi[nt]);
                    }
                }
        }
        __syncthreads();
    }

#pragma unroll
    for (int mt = 0; mt < 4; mt++)
#pragma unroll
        for (int nt = 0; nt < 4; nt++) {
            int row = m0 + wm * 64 + mt * 16 + gid;
            int col = n0 + wn * 32 + nt * 8 + 2 * tig;
            float2 v0 = make_float2(c[mt][nt][0], c[mt][nt][1]);
            float2 v1 = make_float2(c[mt][nt][2], c[mt][nt][3]);
            *(float2*)&C[(size_t)row * N + col]       = v0;
            *(float2*)&C[(size_t)(row + 8) * N + col] = v1;
        }
}

// ---------------------------------------------------------------------------
// RoPE (rotate-half, max_wavelength 10000), applied in place.
// ---------------------------------------------------------------------------
__global__ void rope_kernel(float* __restrict__ X, const int* __restrict__ pos, int stride)
{
    const int s = blockIdx.x;
    const int h = blockIdx.y;
    const int d = threadIdx.x;  // 0..63

    float p = (float)pos[s];
    float inv = powf(10000.0f, -(float)d / 64.0f);
    float sn, cs;
    sincosf(p * inv, &sn, &cs);

    float* base = X + (size_t)s * stride + h * DH;
    float x1 = base[d];
    float x2 = base[d + 64];
    base[d]      = x1 * cs - x2 * sn;
    base[d + 64] = x2 * cs + x1 * sn;
}

// ---------------------------------------------------------------------------
// Causal flash attention with tf32 mma, GQA (8 q-heads per kv-head).
// CTA: 128 q-rows x (64-wide KV tiles); 256 threads = 8 warps, 16 q-rows/warp.
// QK^T uses 3-pass tf32 (error-compensated); PV single-pass.
// ---------------------------------------------------------------------------
#define Q_PITCH 132
#define K_PITCH 132
#define V_PITCH 132
#define P_PITCH 72

#define FL_QS_F   (128 * Q_PITCH)                    // 16896
#define FL_U_F    (128 * P_PITCH)                    // 9216 (>= 64*K_PITCH=8448)
#define FL_VS_F   (64 * V_PITCH)                     // 8448
#define FL_SMEM_BYTES ((FL_QS_F + FL_U_F + FL_VS_F) * 4)  // 138240

__global__ __launch_bounds__(256) void flash_mma(
    const float* __restrict__ Q, const float* __restrict__ K,
    const float* __restrict__ V, float* __restrict__ O)
{
    extern __shared__ float sm[];
    float* qs = sm;                  // [128][Q_PITCH]
    float* ks = sm + FL_QS_F;        // [64][K_PITCH]   (aliased with ps)
    float* ps = sm + FL_QS_F;        // [128][P_PITCH]
    float* vs = sm + FL_QS_F + FL_U_F;  // [64][V_PITCH]

    const int qb   = (gridDim.x - 1) - blockIdx.x;  // heavy blocks first
    const int h    = blockIdx.y;
    const int hk   = h >> 3;
    const int tid  = threadIdx.x;
    const int lane = tid & 31;
    const int w    = tid >> 5;
    const int gid  = lane >> 2;
    const int tig  = lane & 3;

    const float scale = 0.08838834764831845f;  // 1/sqrt(128)

    // load Q tile (pre-scaled)
#pragma unroll
    for (int l = 0; l < 16; l++) {
        int i = tid + l * 256;
        int r = i >> 5, c4 = (i & 31) << 2;
        float4 v = *(const float4*)&Q[(size_t)(qb * 128 + r) * DQTOT + h * DH + c4];
        v.x *= scale; v.y *= scale; v.z *= scale; v.w *= scale;
        *(float4*)&qs[r * Q_PITCH + c4] = v;
    }

    float m_[2], l_[2];
    m_[0] = m_[1] = -1e30f;
    l_[0] = l_[1] = 0.f;
    float o[16][4];
#pragma unroll
    for (int nt = 0; nt < 16; nt++)
#pragma unroll
        for (int q = 0; q < 4; q++) o[nt][q] = 0.f;

    const int kbmax = 2 * qb + 1;

    for (int kb = 0; kb <= kbmax; kb++) {
        __syncthreads();  // prior iter's PV reads (ps, vs) complete; Q visible on 1st

        // load K, V tiles (64 x 128)
#pragma unroll
        for (int l = 0; l < 8; l++) {
            int i = tid + l * 256;
            int r = i >> 5, c4 = (i & 31) << 2;
            *(float4*)&ks[r * K_PITCH + c4] =
                *(const float4*)&K[(size_t)(kb * 64 + r) * DKVTOT + hk * DH + c4];
            *(float4*)&vs[r * V_PITCH + c4] =
                *(const float4*)&V[(size_t)(kb * 64 + r) * DKVTOT + hk * DH + c4];
        }
        __syncthreads();

        // S = Q @ K^T (3-pass tf32), warp owns 16 rows x 64 cols
        float s[8][4];
#pragma unroll
        for (int nt = 0; nt < 8; nt++)
#pragma unroll
            for (int q = 0; q < 4; q++) s[nt][q] = 0.f;

#pragma unroll
        for (int k8 = 0; k8 < 16; k8++) {
            const int kc = k8 * 8 + tig;
            const int rm = w * 16 + gid;
            uint32_t ahi[4], alo[4];
            splitf(qs[rm * Q_PITCH + kc],            ahi[0], alo[0]);
            splitf(qs[(rm + 8) * Q_PITCH + kc],      ahi[1], alo[1]);
            splitf(qs[rm * Q_PITCH + kc + 4],        ahi[2], alo[2]);
            splitf(qs[(rm + 8) * Q_PITCH + kc + 4],  ahi[3], alo[3]);
#pragma unroll
            for (int nt = 0; nt < 8; nt++) {
                const int nr = nt * 8 + gid;
                uint32_t bhi[2], blo[2];
                splitf(ks[nr * K_PITCH + kc],     bhi[0], blo[0]);
                splitf(ks[nr * K_PITCH + kc + 4], bhi[1], blo[1]);
                mma8(s[nt], ahi, bhi);
                mma8(s[nt], ahi, blo);
                mma8(s[nt], alo, bhi);
            }
        }

        // causal mask (only diagonal tiles)
        if (kb >= 2 * qb) {
            const int row0 = qb * 128 + w * 16 + gid;
#pragma unroll
            for (int nt = 0; nt < 8; nt++) {
                int col = kb * 64 + nt * 8 + 2 * tig;
                if (col     > row0)     s[nt][0] = -1e30f;
                if (col + 1 > row0)     s[nt][1] = -1e30f;
                if (col     > row0 + 8) s[nt][2] = -1e30f;
                if (col + 1 > row0 + 8) s[nt][3] = -1e30f;
            }
        }

        // online softmax (rows r0 = w*16+gid, r1 = r0+8)
        float mx0 = -1e30f, mx1 = -1e30f;
#pragma unroll
        for (int nt = 0; nt < 8; nt++) {
            mx0 = fmaxf(mx0, fmaxf(s[nt][0], s[nt][1]));
            mx1 = fmaxf(mx1, fmaxf(s[nt][2], s[nt][3]));
        }
#pragma unroll
        for (int off = 1; off <= 2; off <<= 1) {
            mx0 = fmaxf(mx0, __shfl_xor_sync(0xffffffffu, mx0, off));
            mx1 = fmaxf(mx1, __shfl_xor_sync(0xffffffffu, mx1, off));
        }
        float mn0 = fmaxf(m_[0], mx0);
        float mn1 = fmaxf(m_[1], mx1);
        float f0 = __expf(m_[0] - mn0);
        float f1 = __expf(m_[1] - mn1);
        m_[0] = mn0; m_[1] = mn1;

        float p[8][4];
        float rs0 = 0.f, rs1 = 0.f;
#pragma unroll
        for (int nt = 0; nt < 8; nt++) {
            p[nt][0] = __expf(s[nt][0] - mn0);
            p[nt][1] = __expf(s[nt][1] - mn0);
            p[nt][2] = __expf(s[nt][2] - mn1);
            p[nt][3] = __expf(s[nt][3] - mn1);
            rs0 += p[nt][0] + p[nt][1];
            rs1 += p[nt][2] + p[nt][3];
        }
#pragma unroll
        for (int off = 1; off <= 2; off <<= 1) {
            rs0 += __shfl_xor_sync(0xffffffffu, rs0, off);
            rs1 += __shfl_xor_sync(0xffffffffu, rs1, off);
        }
        l_[0] = l_[0] * f0 + rs0;
        l_[1] = l_[1] * f1 + rs1;
#pragma unroll
        for (int nt = 0; nt < 16; nt++) {
            o[nt][0] *= f0; o[nt][1] *= f0;
            o[nt][2] *= f1; o[nt][3] *= f1;
        }

        __syncthreads();  // all warps done reading ks before overwriting with ps

        {
            const int r0 = w * 16 + gid;
#pragma unroll
            for (int nt = 0; nt < 8; nt++) {
                int col = nt * 8 + 2 * tig;
                *(float2*)&ps[r0 * P_PITCH + col]       = make_float2(p[nt][0], p[nt][1]);
                *(float2*)&ps[(r0 + 8) * P_PITCH + col] = make_float2(p[nt][2], p[nt][3]);
            }
        }
        __syncthreads();  // ps visible

        // O += P @ V (single-pass tf32)
#pragma unroll
        for (int j = 0; j < 8; j++) {
            const int ar = w * 16 + gid;
            const int kc = j * 8 + tig;
            uint32_t a[4];
            a[0] = f2tf(ps[ar * P_PITCH + kc]);
            a[1] = f2tf(ps[(ar + 8) * P_PITCH + kc]);
            a[2] = f2tf(ps[ar * P_PITCH + kc + 4]);
            a[3] = f2tf(ps[(ar + 8) * P_PITCH + kc + 4]);
#pragma unroll
            for (int nt = 0; nt < 16; nt++) {
                uint32_t b[2];
                b[0] = f2tf(vs[kc * V_PITCH + nt * 8 + gid]);
                b[1] = f2tf(vs[(kc + 4) * V_PITCH + nt * 8 + gid]);
                mma8(o[nt], a, b);
            }
        }
    }

    // epilogue: normalize and store
    {
        const float il0 = 1.0f / l_[0];
        const float il1 = 1.0f / l_[1];
        const int row0 = qb * 128 + w * 16 + gid;
#pragma unroll
        for (int nt = 0; nt < 16; nt++) {
            int col = h * DH + nt * 8 + 2 * tig;
            *(float2*)&O[(size_t)row0 * DQTOT + col] =
                make_float2(o[nt][0] * il0, o[nt][1] * il0);
            *(float2*)&O[(size_t)(row0 + 8) * DQTOT + col] =
                make_float2(o[nt][2] * il1, o[nt][3] * il1);
        }
    }
}

// ---------------------------------------------------------------------------
// Launch
// ---------------------------------------------------------------------------
extern "C" void kernel_launch(void* const* d_in, const int* in_sizes, int n_in,
                              void* d_out, int out_size)
{
    const float* X  = (const float*)d_in[0];
    const float* Wq = (const float*)d_in[1];
    const float* Wk = (const float*)d_in[2];
    const float* Wv = (const float*)d_in[3];
    const float* Wo = (const float*)d_in[4];
    const int*  pos = (const int*)d_in[5];
    float* out = (float*)d_out;

    float *Qp, *Kp, *Vp, *Op;
    cudaGetSymbolAddress((void**)&Qp, g_Q);
    cudaGetSymbolAddress((void**)&Kp, g_K);
    cudaGetSymbolAddress((void**)&Vp, g_V);
    cudaGetSymbolAddress((void**)&Op, g_O);

    cudaFuncSetAttribute(flash_mma,
                         cudaFuncAttributeMaxDynamicSharedMemorySize,
                         FL_SMEM_BYTES);

    // QKV projections (Q/K error-compensated; V single-pass)
    tgemm<3><<<dim3(DQTOT / 128, SEQ / 128), 256>>>(X, Wq, Qp, SEQ, DQTOT, HID);
    tgemm<3><<<dim3(DKVTOT / 128, SEQ / 128), 256>>>(X, Wk, Kp, SEQ, DKVTOT, HID);
    tgemm<1><<<dim3(DKVTOT / 128, SEQ / 128), 256>>>(X, Wv, Vp, SEQ, DKVTOT, HID);

    // RoPE on Q and K
    rope_kernel<<<dim3(SEQ, NHQ), 64>>>(Qp, pos, DQTOT);
    rope_kernel<<<dim3(SEQ, NHKV), 64>>>(Kp, pos, DKVTOT);

    // causal flash attention (tensor-core)
    flash_mma<<<dim3(SEQ / 128, NHQ), 256, FL_SMEM_BYTES>>>(Qp, Kp, Vp, Op);

    // output projection (single-pass tf32)
    tgemm<1><<<dim3(HID / 128, SEQ / 128), 256>>>(Op, Wo, out, SEQ, HID, DQTOT);
}